// round 10
// baseline (speedup 1.0000x reference)
#include <cuda_runtime.h>

#define BB 4
#define NH 8
#define DD 16
#define LC 1024
#define WCC 32
#define LF 4096
#define WFF 64
#define TOPK 8
#define KVPAD 20
#define CPAD 20

typedef unsigned long long ull;

__device__ float g_qc[BB*NH*LC*DD];
__device__ float g_kc[BB*NH*LC*DD];
__device__ float g_vc[BB*NH*LC*DD];
__device__ float g_qf[BB*NH*LF*DD];
__device__ float g_kf[BB*NH*LF*DD];
__device__ float g_vf[BB*NH*LF*DD];
__device__ float g_msg0[BB*NH*LC*DD];
__device__ int   g_topk[BB*NH*LC*TOPK];

__device__ __forceinline__ float2 f2unpack(ull v) {
    float lo, hi; asm("mov.b64 {%0, %1}, %2;" : "=f"(lo), "=f"(hi) : "l"(v));
    return make_float2(lo, hi);
}
__device__ __forceinline__ ull f2dup(float x) {
    ull r; asm("mov.b64 %0, {%1, %1};" : "=l"(r) : "f"(x)); return r;
}
__device__ __forceinline__ ull f2fma(ull a, ull b, ull c) {
    ull d; asm("fma.rn.f32x2 %0, %1, %2, %3;" : "=l"(d) : "l"(a), "l"(b), "l"(c));
    return d;
}
__device__ __forceinline__ float ex2f(float x) {
    float r; asm("ex2.approx.ftz.f32 %0, %1;" : "=f"(r) : "f"(x)); return r;
}

// ---------------- tiled transpose: [BH,16,P] -> [BH,P,16] ----------------
__global__ void __launch_bounds__(256) transpose3_kernel(
        const float* __restrict__ q, const float* __restrict__ k,
        const float* __restrict__ v, float* __restrict__ oq,
        float* __restrict__ ok, float* __restrict__ ov, int P, float qscale) {
    __shared__ float tile[16 * 260];
    int z = blockIdx.z;
    const float* in = (z == 0) ? q : (z == 1) ? k : v;
    float* out = (z == 0) ? oq : (z == 1) ? ok : ov;
    float scale = (z == 0) ? qscale : 1.f;
    int bh = blockIdx.y, p0 = blockIdx.x * 256, t = threadIdx.x;
    const float4* src = reinterpret_cast<const float4*>(in + (size_t)bh * DD * P + p0);
    int Pq = P >> 2;
#pragma unroll
    for (int j = 0; j < 4; j++) {
        int f = t + 256 * j;
        int d = f >> 6, c4 = f & 63;
        float4 val = src[(size_t)d * Pq + c4];
        val.x *= scale; val.y *= scale; val.z *= scale; val.w *= scale;
        *reinterpret_cast<float4*>(&tile[d * 260 + c4 * 4]) = val;
    }
    __syncthreads();
    float o[16];
#pragma unroll
    for (int d = 0; d < 16; d++) o[d] = tile[d * 260 + t];
    float4* dst = reinterpret_cast<float4*>(out + ((size_t)bh * P + p0 + t) * DD);
    dst[0] = make_float4(o[0], o[1], o[2], o[3]);
    dst[1] = make_float4(o[4], o[5], o[6], o[7]);
    dst[2] = make_float4(o[8], o[9], o[10], o[11]);
    dst[3] = make_float4(o[12], o[13], o[14], o[15]);
}

__device__ __forceinline__ unsigned fsort(float f) {
    unsigned u = __float_as_uint(f);
    return u ^ (((unsigned)((int)u >> 31)) | 0x80000000u);
}

__device__ __forceinline__ void loadk(const float* __restrict__ p, ull* kd) {
    ulonglong2 a = *(const ulonglong2*)(p);
    ulonglong2 b = *(const ulonglong2*)(p + 4);
    ulonglong2 c = *(const ulonglong2*)(p + 8);
    ulonglong2 d = *(const ulonglong2*)(p + 12);
    kd[0] = a.x; kd[1] = a.y; kd[2] = b.x; kd[3] = b.y;
    kd[4] = c.x; kd[5] = c.y; kd[6] = d.x; kd[7] = d.y;
}

// packed-d dot: bit-identical chain in main pass AND rescan
__device__ __forceinline__ float srowr(const ull* __restrict__ q,
                                       const ull* __restrict__ kd) {
    ull a = 0ull;
#pragma unroll
    for (int dp = 0; dp < 8; dp++) a = f2fma(q[dp], kd[dp], a);
    float2 u = f2unpack(a);
    return u.x + u.y;
}

// branchless per-lane top-2; strict > keeps earliest (=lowest) col on ties
__device__ __forceinline__ void upd2(float s, int c, float& v1, int& c1,
                                     float& v2, int& c2) {
    bool p = s > v1;
    bool q = s > v2;
    float tv = q ? s : v2; int tc = q ? c : c2;
    v2 = p ? v1 : tv;  c2 = p ? c1 : tc;
    v1 = p ? s : v1;   c1 = p ? c : c1;
}

// exact top-8 merge: REDUX max on value, REDUX min on col; rescan recomputes
__device__ __forceinline__ void topk8m(float v1, int c1, float v2, int c2,
                                       const ull* __restrict__ q,
                                       const float* __restrict__ sK,
                                       int lane, int* __restrict__ gout) {
    int cc = 0, my = 0;
#pragma unroll 1
    for (int pick = 0; pick < TOPK; pick++) {
        unsigned key = fsort(v1);
        unsigned M = __reduce_max_sync(0xffffffffu, key);
        unsigned cand = (key == M) ? (unsigned)c1 : 0xffffffffu;
        unsigned C = __reduce_min_sync(0xffffffffu, cand);
        if (lane == pick) my = (int)C;
        if (key == M && (unsigned)c1 == C) {
            float tval = v1; int tcol = c1;
            cc++;
            if (cc == 1) { v1 = v2; c1 = c2; }
            else {
                v1 = -1e30f; c1 = 0x7fffffff;
#pragma unroll 1
                for (int i = 0; i < 32; i++) {
                    int s = i * 32 + lane;
                    ull kd[8];
                    loadk(&sK[s * CPAD], kd);
                    float sc = srowr(q, kd);
                    bool below = (sc < tval) || (sc == tval && s > tcol);
                    bool better = (sc > v1) || (sc == v1 && s < c1);
                    if (below && better) { v1 = sc; c1 = s; }
                }
            }
        }
    }
    if (lane < TOPK) gout[lane] = my;
}

// ---------------- coarse: fused, 256 threads, 8 warps x 4 rows -----------
#define CSMEM_BYTES (2 * LC * CPAD * 4)

__global__ void __launch_bounds__(256, 1) coarse_kernel() {
    extern __shared__ float sm[];
    float* sK = sm;                  // 1024 x 20
    float* sV = sm + LC * CPAD;      // 1024 x 20
    int tid = threadIdx.x, w = tid >> 5, lane = tid & 31;
    int bh = blockIdx.y;

    const float4* K4 = (const float4*)(g_kc + (size_t)bh * LC * DD);
    const float4* V4 = (const float4*)(g_vc + (size_t)bh * LC * DD);
#pragma unroll
    for (int i = tid; i < LC * DD / 4; i += 256) {
        int s = i >> 2, j = i & 3;
        *(float4*)&sK[s * CPAD + j * 4] = K4[i];
        *(float4*)&sV[s * CPAD + j * 4] = V4[i];
    }

    int r0 = blockIdx.x * 32 + w * 4;
    const ull* Qg = (const ull*)(g_qc + ((size_t)bh * LC + r0) * DD);
    ull q[4][8];
#pragma unroll
    for (int r = 0; r < 4; r++)
#pragma unroll
        for (int dp = 0; dp < 8; dp++) q[r][dp] = Qg[r * 8 + dp];
    __syncthreads();

    float v1[4], v2[4]; int c1[4], c2[4];
    float sums[4];
    ull acc[4][8];
#pragma unroll
    for (int r = 0; r < 4; r++) {
        v1[r] = -1e30f; v2[r] = -1e30f;
        c1[r] = 0x7fffffff; c2[r] = 0x7fffffff;
        sums[r] = 0.f;
#pragma unroll
        for (int dp = 0; dp < 8; dp++) acc[r][dp] = 0ull;
    }

#pragma unroll 2
    for (int i = 0; i < 32; i++) {
        int s = i * 32 + lane;
        ull kd[8];
        loadk(&sK[s * CPAD], kd);
        float e[4];
#pragma unroll
        for (int r = 0; r < 4; r++) {
            float sc = srowr(q[r], kd);
            upd2(sc, s, v1[r], c1[r], v2[r], c2[r]);
            float ee = ex2f(sc);          // log2e folded into Q scale
            sums[r] += ee;
            e[r] = ee;
        }
        ull vd[8];
        loadk(&sV[s * CPAD], vd);
#pragma unroll
        for (int r = 0; r < 4; r++) {
            ull ed = f2dup(e[r]);
#pragma unroll
            for (int dp = 0; dp < 8; dp++)
                acc[r][dp] = f2fma(ed, vd[dp], acc[r][dp]);
        }
    }

    // exact top-8 per row (reads sK)
    int* tb = g_topk + ((size_t)bh * LC + r0) * TOPK;
#pragma unroll 1
    for (int r = 0; r < 4; r++)
        topk8m(v1[r], c1[r], v2[r], c2[r], q[r], sK, lane, tb + r * TOPK);

    // row sums
#pragma unroll
    for (int off = 16; off; off >>= 1) {
#pragma unroll
        for (int r = 0; r < 4; r++)
            sums[r] += __shfl_xor_sync(0xffffffffu, sums[r], off);
    }
    float rs[4];
#pragma unroll
    for (int r = 0; r < 4; r++) rs[r] = 1.f / sums[r];

    __syncthreads();   // done with sK -> reuse as reduce staging
    float* st = sK + w * (4 * 16 * 33);   // 2112 floats/warp, 8 warps fits 80KB
#pragma unroll
    for (int r = 0; r < 4; r++)
#pragma unroll
        for (int dp = 0; dp < 8; dp++) {
            float2 u = f2unpack(acc[r][dp]);
            st[(r * 16 + 2 * dp) * 33 + lane] = u.x;
            st[(r * 16 + 2 * dp + 1) * 33 + lane] = u.y;
        }
    __syncwarp();
    float* mp = g_msg0 + ((size_t)bh * LC + r0) * DD;
    int hi = lane >> 4, d = lane & 15;
#pragma unroll
    for (int half = 0; half < 2; half++) {
        int row = half * 2 + hi;
        float a = 0.f;
#pragma unroll
        for (int j = 0; j < 32; j++) a += st[(row * 16 + d) * 33 + j];
        float rsv = hi ? rs[half * 2 + 1] : rs[half * 2];
        mp[row * DD + d] = a * rsv;
    }
}

// ---------------- fine level + combine ----------------
__device__ __forceinline__ float dot16(float4 a0, float4 a1, float4 a2, float4 a3,
                                       float4 b0, float4 b1, float4 b2, float4 b3) {
    float s = a0.x*b0.x + a0.y*b0.y + a0.z*b0.z + a0.w*b0.w;
    s += a1.x*b1.x + a1.y*b1.y + a1.z*b1.z + a1.w*b1.w;
    s += a2.x*b2.x + a2.y*b2.y + a2.z*b2.z + a2.w*b2.w;
    s += a3.x*b3.x + a3.y*b3.y + a3.z*b3.z + a3.w*b3.w;
    return s;
}

__global__ void __launch_bounds__(256) fine_kernel(const float* __restrict__ wptr,
                                                   float* __restrict__ out) {
    __shared__ float sQ[8][4][16];
    __shared__ float sKP[8][32][KVPAD];   // K tiles, later overlaid by P
    __shared__ float sV[8][32][KVPAD];
    int tid = threadIdx.x, w = tid >> 5, lane = tid & 31;
    int gw = blockIdx.x * 8 + w;
    int bh = gw >> 10, l = gw & 1023;
    int b = bh >> 3, h = bh & 7;
    int lh = l >> 5, lw = l & 31;

    float w0 = wptr[0], w1 = wptr[1];
    float mw = fmaxf(w0, w1);
    float ew0 = __expf(w0 - mw), ew1 = __expf(w1 - mw);
    float rw = __fdividef(1.f, ew0 + ew1);
    float wa = ew0 * rw, wb = ew1 * rw;

    int cr = lane >> 2, off2 = lane & 3, ox = off2 >> 1, oy = off2 & 1;
    int cidx = g_topk[((size_t)bh * LC + l) * TOPK + cr];
    int py = cidx >> 5, px = cidx & (WCC - 1);
    int pos = (2 * py + ox) * WFF + 2 * px + oy;

    if (lane < 16) {
        int qq = lane >> 2, j = lane & 3;
        int qpos = (2 * lh + (qq >> 1)) * WFF + 2 * lw + (qq & 1);
        float4 qv = ((const float4*)(g_qf + ((size_t)bh * LF + qpos) * DD))[j];
        *reinterpret_cast<float4*>(&sQ[w][qq][4 * j]) = qv;
    }

    const float* kbase = g_kf + (size_t)bh * LF * DD;
    const float* vbase = g_vf + (size_t)bh * LF * DD;
    int cj = lane >> 2, j4 = (lane & 3) * 4;
#pragma unroll
    for (int rep = 0; rep < 4; rep++) {
        int c = rep * 8 + cj;
        int pc = __shfl_sync(0xffffffffu, pos, c);
        float4 kv = *(const float4*)(kbase + (size_t)pc * DD + j4);
        *reinterpret_cast<float4*>(&sKP[w][c][j4]) = kv;
        float4 vv = *(const float4*)(vbase + (size_t)pc * DD + j4);
        *reinterpret_cast<float4*>(&sV[w][c][j4]) = vv;
    }
    __syncwarp();

    const float* kp = &sKP[w][lane][0];
    float4 k0 = *(const float4*)(kp);
    float4 k1 = *(const float4*)(kp + 4);
    float4 k2 = *(const float4*)(kp + 8);
    float4 k3 = *(const float4*)(kp + 12);
    __syncwarp();   // all k regs loaded before P overlays the buffer

    float p[4];
#pragma unroll
    for (int qq = 0; qq < 4; qq++) {
        const float4* q4 = (const float4*)sQ[w][qq];
        float sc = dot16(q4[0], q4[1], q4[2], q4[3], k0, k1, k2, k3);
        float m = sc;
#pragma unroll
        for (int o = 16; o; o >>= 1) m = fmaxf(m, __shfl_xor_sync(0xffffffffu, m, o));
        float e = ex2f(sc - m);
        float s = e;
#pragma unroll
        for (int o = 16; o; o >>= 1) s += __shfl_xor_sync(0xffffffffu, s, o);
        p[qq] = __fdividef(e, s);
    }
    *reinterpret_cast<float4*>(&sKP[w][lane][0]) = make_float4(p[0], p[1], p[2], p[3]);
    __syncwarp();

    int qq = lane >> 3, dp = lane & 7, d0 = dp * 2;
    float accx = 0.f, accy = 0.f;
#pragma unroll
    for (int c = 0; c < 32; c++) {
        float pc = sKP[w][c][qq];
        float2 vv = *reinterpret_cast<const float2*>(&sV[w][c][d0]);
        accx += pc * vv.x;
        accy += pc * vv.y;
    }
    const float* m0p = g_msg0 + ((size_t)bh * LC + l) * DD + d0;
    float o0 = wa * m0p[0] + wb * accx;
    float o1 = wa * m0p[1] + wb * accy;
    int opos = (2 * lh + (qq >> 1)) * WFF + 2 * lw + (qq & 1);
    float* op = out + (((size_t)b * LF + opos) * NH + h) * DD + d0;
    *reinterpret_cast<float2*>(op) = make_float2(o0, o1);
}

extern "C" void kernel_launch(void* const* d_in, const int* in_sizes, int n_in,
                              void* d_out, int out_size) {
    (void)in_sizes; (void)n_in; (void)out_size;
    const float* qf = (const float*)d_in[0];
    const float* qc = (const float*)d_in[1];
    const float* kf = (const float*)d_in[2];
    const float* kc = (const float*)d_in[3];
    const float* vf = (const float*)d_in[4];
    const float* vc = (const float*)d_in[5];
    const float* wt = (const float*)d_in[6];
    float* out = (float*)d_out;

    void *p_qc, *p_kc, *p_vc, *p_qf, *p_kf, *p_vf;
    cudaGetSymbolAddress(&p_qc, g_qc);
    cudaGetSymbolAddress(&p_kc, g_kc);
    cudaGetSymbolAddress(&p_vc, g_vc);
    cudaGetSymbolAddress(&p_qf, g_qf);
    cudaGetSymbolAddress(&p_kf, g_kf);
    cudaGetSymbolAddress(&p_vf, g_vf);

    const float qscale = 0.25f * 1.4426950408889634f;  // temp * log2(e)
    transpose3_kernel<<<dim3(LC / 256, 32, 3), 256>>>(
        qc, kc, vc, (float*)p_qc, (float*)p_kc, (float*)p_vc, LC, qscale);
    transpose3_kernel<<<dim3(LF / 256, 32, 3), 256>>>(
        qf, kf, vf, (float*)p_qf, (float*)p_kf, (float*)p_vf, LF, qscale);

    cudaFuncSetAttribute(coarse_kernel, cudaFuncAttributeMaxDynamicSharedMemorySize,
                         CSMEM_BYTES);
    coarse_kernel<<<dim3(32, 32), 256, CSMEM_BYTES>>>();

    fine_kernel<<<4096, 256>>>(wt, out);
}

// round 11
// speedup vs baseline: 1.3581x; 1.3581x over previous
#include <cuda_runtime.h>

#define BB 4
#define NH 8
#define DD 16
#define LC 1024
#define WCC 32
#define LF 4096
#define WFF 64
#define TOPK 8
#define KVPAD 20

typedef unsigned long long ull;

__device__ float g_qc[BB*NH*LC*DD];
__device__ float g_kc[BB*NH*LC*DD];
__device__ float g_vc[BB*NH*LC*DD];
__device__ float g_qf[BB*NH*LF*DD];
__device__ float g_kf[BB*NH*LF*DD];
__device__ float g_vf[BB*NH*LF*DD];
__device__ float g_msg0[BB*NH*LC*DD];
__device__ int   g_topk[BB*NH*LC*TOPK];

__device__ __forceinline__ float2 f2unpack(ull v) {
    float lo, hi; asm("mov.b64 {%0, %1}, %2;" : "=f"(lo), "=f"(hi) : "l"(v));
    return make_float2(lo, hi);
}
__device__ __forceinline__ ull f2dup(float x) {
    ull r; asm("mov.b64 %0, {%1, %1};" : "=l"(r) : "f"(x)); return r;
}
__device__ __forceinline__ ull f2fma(ull a, ull b, ull c) {
    ull d; asm("fma.rn.f32x2 %0, %1, %2, %3;" : "=l"(d) : "l"(a), "l"(b), "l"(c));
    return d;
}
__device__ __forceinline__ ull f2add(ull a, ull b) {
    ull d; asm("add.rn.f32x2 %0, %1, %2;" : "=l"(d) : "l"(a), "l"(b));
    return d;
}
__device__ __forceinline__ float ex2f(float x) {
    float r; asm("ex2.approx.ftz.f32 %0, %1;" : "=f"(r) : "f"(x)); return r;
}

// ---------------- tiled transpose: [BH,16,P] -> [BH,P,16] ----------------
__global__ void __launch_bounds__(256) transpose3_kernel(
        const float* __restrict__ q, const float* __restrict__ k,
        const float* __restrict__ v, float* __restrict__ oq,
        float* __restrict__ ok, float* __restrict__ ov, int P, float qscale) {
    __shared__ float tile[16 * 260];
    int z = blockIdx.z;
    const float* in = (z == 0) ? q : (z == 1) ? k : v;
    float* out = (z == 0) ? oq : (z == 1) ? ok : ov;
    float scale = (z == 0) ? qscale : 1.f;
    int bh = blockIdx.y, p0 = blockIdx.x * 256, t = threadIdx.x;
    const float4* src = reinterpret_cast<const float4*>(in + (size_t)bh * DD * P + p0);
    int Pq = P >> 2;
#pragma unroll
    for (int j = 0; j < 4; j++) {
        int f = t + 256 * j;
        int d = f >> 6, c4 = f & 63;
        float4 val = src[(size_t)d * Pq + c4];
        val.x *= scale; val.y *= scale; val.z *= scale; val.w *= scale;
        *reinterpret_cast<float4*>(&tile[d * 260 + c4 * 4]) = val;
    }
    __syncthreads();
    float o[16];
#pragma unroll
    for (int d = 0; d < 16; d++) o[d] = tile[d * 260 + t];
    float4* dst = reinterpret_cast<float4*>(out + ((size_t)bh * P + p0 + t) * DD);
    dst[0] = make_float4(o[0], o[1], o[2], o[3]);
    dst[1] = make_float4(o[4], o[5], o[6], o[7]);
    dst[2] = make_float4(o[8], o[9], o[10], o[11]);
    dst[3] = make_float4(o[12], o[13], o[14], o[15]);
}

// ---------------- coarse: lane-per-row, fused, 1 wave --------------------
// grid (4, 32), 256 threads. Each lane owns one query row; K/V rows are
// warp-uniform smem broadcasts. Per-lane exact top-8 by sorted insertion.
#define CSMEM_BYTES (2 * LC * DD * 4)

__global__ void __launch_bounds__(256, 1) coarse_kernel() {
    extern __shared__ float sm[];
    float* sK = sm;             // 1024 x 16, contiguous (broadcast reads)
    float* sV = sm + LC * DD;   // 1024 x 16
    int tid = threadIdx.x, w = tid >> 5, lane = tid & 31;
    int bh = blockIdx.y;

    {
        const float4* K4 = (const float4*)(g_kc + (size_t)bh * LC * DD);
        const float4* V4 = (const float4*)(g_vc + (size_t)bh * LC * DD);
        float4* sK4 = (float4*)sK;
        float4* sV4 = (float4*)sV;
#pragma unroll
        for (int i = tid; i < LC * DD / 4; i += 256) {
            sK4[i] = K4[i];
            sV4[i] = V4[i];
        }
    }

    int row = blockIdx.x * 256 + w * 32 + lane;
    const ull* Qg = (const ull*)(g_qc + ((size_t)bh * LC + row) * DD);
    ull q[8];
#pragma unroll
    for (int dp = 0; dp < 8; dp++) q[dp] = Qg[dp];
    __syncthreads();

    float tv[8]; int tc[8];
#pragma unroll
    for (int k = 0; k < 8; k++) { tv[k] = -3e38f; tc[k] = 0; }
    ull acc[8];
#pragma unroll
    for (int dp = 0; dp < 8; dp++) acc[dp] = 0ull;
    float sum = 0.f;

#pragma unroll 2
    for (int j = 0; j < LC; j++) {
        const ull* kr = (const ull*)(sK + j * DD);
        ull a0 = 0ull, a1 = 0ull;
        a0 = f2fma(q[0], kr[0], a0); a1 = f2fma(q[1], kr[1], a1);
        a0 = f2fma(q[2], kr[2], a0); a1 = f2fma(q[3], kr[3], a1);
        a0 = f2fma(q[4], kr[4], a0); a1 = f2fma(q[5], kr[5], a1);
        a0 = f2fma(q[6], kr[6], a0); a1 = f2fma(q[7], kr[7], a1);
        float2 u = f2unpack(f2add(a0, a1));
        float sc = u.x + u.y;
        float e = ex2f(sc);            // log2e folded into Q scale
        sum += e;
        ull ed = f2dup(e);
        const ull* vr = (const ull*)(sV + j * DD);
#pragma unroll
        for (int dp = 0; dp < 8; dp++) acc[dp] = f2fma(ed, vr[dp], acc[dp]);
        // exact top-8: strict > + ascending j == lax.top_k tie semantics
        if (sc > tv[7]) {
            tv[7] = sc; tc[7] = j;
#pragma unroll
            for (int k = 7; k >= 1; k--) {
                bool sw = tv[k] > tv[k - 1];
                float va = sw ? tv[k - 1] : tv[k];
                float vb = sw ? tv[k] : tv[k - 1];
                int ia = sw ? tc[k - 1] : tc[k];
                int ib = sw ? tc[k] : tc[k - 1];
                tv[k] = va; tv[k - 1] = vb;
                tc[k] = ia; tc[k - 1] = ib;
            }
        }
    }

    int* tb = g_topk + ((size_t)bh * LC + row) * TOPK;
    *(int4*)tb = make_int4(tc[0], tc[1], tc[2], tc[3]);
    *(int4*)(tb + 4) = make_int4(tc[4], tc[5], tc[6], tc[7]);

    float rs = 1.f / sum;
    float o[16];
#pragma unroll
    for (int dp = 0; dp < 8; dp++) {
        float2 u = f2unpack(acc[dp]);
        o[2 * dp] = u.x * rs;
        o[2 * dp + 1] = u.y * rs;
    }
    float4* mp = (float4*)(g_msg0 + ((size_t)bh * LC + row) * DD);
    mp[0] = make_float4(o[0], o[1], o[2], o[3]);
    mp[1] = make_float4(o[4], o[5], o[6], o[7]);
    mp[2] = make_float4(o[8], o[9], o[10], o[11]);
    mp[3] = make_float4(o[12], o[13], o[14], o[15]);
}

// ---------------- fine level + combine ----------------
__device__ __forceinline__ float dot16(float4 a0, float4 a1, float4 a2, float4 a3,
                                       float4 b0, float4 b1, float4 b2, float4 b3) {
    float s = a0.x*b0.x + a0.y*b0.y + a0.z*b0.z + a0.w*b0.w;
    s += a1.x*b1.x + a1.y*b1.y + a1.z*b1.z + a1.w*b1.w;
    s += a2.x*b2.x + a2.y*b2.y + a2.z*b2.z + a2.w*b2.w;
    s += a3.x*b3.x + a3.y*b3.y + a3.z*b3.z + a3.w*b3.w;
    return s;
}

__global__ void __launch_bounds__(256) fine_kernel(const float* __restrict__ wptr,
                                                   float* __restrict__ out) {
    __shared__ float sQ[8][4][16];
    __shared__ float sKP[8][32][KVPAD];   // K tiles, later overlaid by P
    __shared__ float sV[8][32][KVPAD];
    int tid = threadIdx.x, w = tid >> 5, lane = tid & 31;
    int gw = blockIdx.x * 8 + w;
    int bh = gw >> 10, l = gw & 1023;
    int b = bh >> 3, h = bh & 7;
    int lh = l >> 5, lw = l & 31;

    float w0 = wptr[0], w1 = wptr[1];
    float mw = fmaxf(w0, w1);
    float ew0 = __expf(w0 - mw), ew1 = __expf(w1 - mw);
    float rw = __fdividef(1.f, ew0 + ew1);
    float wa = ew0 * rw, wb = ew1 * rw;

    int cr = lane >> 2, off2 = lane & 3, ox = off2 >> 1, oy = off2 & 1;
    int cidx = g_topk[((size_t)bh * LC + l) * TOPK + cr];
    int py = cidx >> 5, px = cidx & (WCC - 1);
    int pos = (2 * py + ox) * WFF + 2 * px + oy;

    if (lane < 16) {
        int qq = lane >> 2, j = lane & 3;
        int qpos = (2 * lh + (qq >> 1)) * WFF + 2 * lw + (qq & 1);
        float4 qv = ((const float4*)(g_qf + ((size_t)bh * LF + qpos) * DD))[j];
        *reinterpret_cast<float4*>(&sQ[w][qq][4 * j]) = qv;
    }

    const float* kbase = g_kf + (size_t)bh * LF * DD;
    const float* vbase = g_vf + (size_t)bh * LF * DD;
    int cj = lane >> 2, j4 = (lane & 3) * 4;
#pragma unroll
    for (int rep = 0; rep < 4; rep++) {
        int c = rep * 8 + cj;
        int pc = __shfl_sync(0xffffffffu, pos, c);
        float4 kv = *(const float4*)(kbase + (size_t)pc * DD + j4);
        *reinterpret_cast<float4*>(&sKP[w][c][j4]) = kv;
        float4 vv = *(const float4*)(vbase + (size_t)pc * DD + j4);
        *reinterpret_cast<float4*>(&sV[w][c][j4]) = vv;
    }
    __syncwarp();

    const float* kp = &sKP[w][lane][0];
    float4 k0 = *(const float4*)(kp);
    float4 k1 = *(const float4*)(kp + 4);
    float4 k2 = *(const float4*)(kp + 8);
    float4 k3 = *(const float4*)(kp + 12);
    __syncwarp();   // all k regs loaded before P overlays the buffer

    float p[4];
#pragma unroll
    for (int qq = 0; qq < 4; qq++) {
        const float4* q4 = (const float4*)sQ[w][qq];
        float sc = dot16(q4[0], q4[1], q4[2], q4[3], k0, k1, k2, k3);
        float m = sc;
#pragma unroll
        for (int o = 16; o; o >>= 1) m = fmaxf(m, __shfl_xor_sync(0xffffffffu, m, o));
        float e = ex2f(sc - m);
        float s = e;
#pragma unroll
        for (int o = 16; o; o >>= 1) s += __shfl_xor_sync(0xffffffffu, s, o);
        p[qq] = __fdividef(e, s);
    }
    *reinterpret_cast<float4*>(&sKP[w][lane][0]) = make_float4(p[0], p[1], p[2], p[3]);
    __syncwarp();

    int qq = lane >> 3, dp = lane & 7, d0 = dp * 2;
    float accx = 0.f, accy = 0.f;
#pragma unroll
    for (int c = 0; c < 32; c++) {
        float pc = sKP[w][c][qq];
        float2 vv = *reinterpret_cast<const float2*>(&sV[w][c][d0]);
        accx += pc * vv.x;
        accy += pc * vv.y;
    }
    const float* m0p = g_msg0 + ((size_t)bh * LC + l) * DD + d0;
    float o0 = wa * m0p[0] + wb * accx;
    float o1 = wa * m0p[1] + wb * accy;
    int opos = (2 * lh + (qq >> 1)) * WFF + 2 * lw + (qq & 1);
    float* op = out + (((size_t)b * LF + opos) * NH + h) * DD + d0;
    *reinterpret_cast<float2*>(op) = make_float2(o0, o1);
}

extern "C" void kernel_launch(void* const* d_in, const int* in_sizes, int n_in,
                              void* d_out, int out_size) {
    (void)in_sizes; (void)n_in; (void)out_size;
    const float* qf = (const float*)d_in[0];
    const float* qc = (const float*)d_in[1];
    const float* kf = (const float*)d_in[2];
    const float* kc = (const float*)d_in[3];
    const float* vf = (const float*)d_in[4];
    const float* vc = (const float*)d_in[5];
    const float* wt = (const float*)d_in[6];
    float* out = (float*)d_out;

    void *p_qc, *p_kc, *p_vc, *p_qf, *p_kf, *p_vf;
    cudaGetSymbolAddress(&p_qc, g_qc);
    cudaGetSymbolAddress(&p_kc, g_kc);
    cudaGetSymbolAddress(&p_vc, g_vc);
    cudaGetSymbolAddress(&p_qf, g_qf);
    cudaGetSymbolAddress(&p_kf, g_kf);
    cudaGetSymbolAddress(&p_vf, g_vf);

    const float qscale = 0.25f * 1.4426950408889634f;  // temp * log2(e)
    transpose3_kernel<<<dim3(LC / 256, 32, 3), 256>>>(
        qc, kc, vc, (float*)p_qc, (float*)p_kc, (float*)p_vc, LC, qscale);
    transpose3_kernel<<<dim3(LF / 256, 32, 3), 256>>>(
        qf, kf, vf, (float*)p_qf, (float*)p_kf, (float*)p_vf, LF, qscale);

    cudaFuncSetAttribute(coarse_kernel, cudaFuncAttributeMaxDynamicSharedMemorySize,
                         CSMEM_BYTES);
    coarse_kernel<<<dim3(4, 32), 256, CSMEM_BYTES>>>();

    fine_kernel<<<4096, 256>>>(wt, out);
}